// round 1
// baseline (speedup 1.0000x reference)
#include <cuda_runtime.h>
#include <math.h>

#define BATCH 4
#define SEQ   2048
#define EMB   1024
#define NH    16
#define HD    64
#define QKV_LD (3*EMB)
#define LDT   68   // padded row stride for attention smem tiles

// Scratch (allocation-free rule: __device__ globals)
__device__ float g_qkv[(size_t)BATCH * SEQ * 3 * EMB];   // [B*S, 3E]
__device__ float g_ctx[(size_t)BATCH * SEQ * EMB];       // [B*S, E]
__device__ float g_bias[65];                             // mean-over-heads rel bias LUT

// ---------------------------------------------------------------------------
// bias_vec[r] = mean_h rel_bias[r, h],  r in [0, 65)
// ---------------------------------------------------------------------------
__global__ void bias_kernel(const float* __restrict__ rel_bias) {
    int r = threadIdx.x;
    if (r < 65) {
        float s = 0.f;
        #pragma unroll
        for (int h = 0; h < NH; h++) s += rel_bias[r * NH + h];
        g_bias[r] = s * (1.0f / NH);
    }
}

// ---------------------------------------------------------------------------
// C[M,N] = A[M,K] @ B[N,K]^T + bias[N]     (both operands K-major: "NT")
// 128x128 block tile, BK=8, 256 threads, 8x8 per thread.
// ---------------------------------------------------------------------------
__global__ __launch_bounds__(256) void gemm_nt(
    const float* __restrict__ A, const float* __restrict__ B,
    const float* __restrict__ bias, float* __restrict__ C,
    int M, int N, int K)
{
    __shared__ float As[8][132];
    __shared__ float Bs[8][132];

    int t  = threadIdx.x;
    int tx = t & 15, ty = t >> 4;

    const float* Ab = A + (size_t)blockIdx.y * 128 * K;
    const float* Bb = B + (size_t)blockIdx.x * 128 * K;

    int lr = t >> 1;           // 0..127
    int lk = (t & 1) << 2;     // 0 or 4
    const float* ap = Ab + (size_t)lr * K + lk;
    const float* bp = Bb + (size_t)lr * K + lk;

    float acc[8][8];
    #pragma unroll
    for (int i = 0; i < 8; i++)
        #pragma unroll
        for (int j = 0; j < 8; j++) acc[i][j] = 0.f;

    for (int k0 = 0; k0 < K; k0 += 8) {
        float4 av = *(const float4*)(ap + k0);
        float4 bv = *(const float4*)(bp + k0);
        __syncthreads();
        As[lk+0][lr] = av.x; As[lk+1][lr] = av.y;
        As[lk+2][lr] = av.z; As[lk+3][lr] = av.w;
        Bs[lk+0][lr] = bv.x; Bs[lk+1][lr] = bv.y;
        Bs[lk+2][lr] = bv.z; Bs[lk+3][lr] = bv.w;
        __syncthreads();

        #pragma unroll
        for (int kk = 0; kk < 8; kk++) {
            float a[8], b[8];
            *(float4*)(a)     = *(const float4*)(&As[kk][ty*8]);
            *(float4*)(a + 4) = *(const float4*)(&As[kk][ty*8 + 4]);
            *(float4*)(b)     = *(const float4*)(&Bs[kk][tx*8]);
            *(float4*)(b + 4) = *(const float4*)(&Bs[kk][tx*8 + 4]);
            #pragma unroll
            for (int i = 0; i < 8; i++)
                #pragma unroll
                for (int j = 0; j < 8; j++)
                    acc[i][j] = fmaf(a[i], b[j], acc[i][j]);
        }
    }

    int n0 = blockIdx.x * 128 + tx * 8;
    int m0 = blockIdx.y * 128 + ty * 8;
    float bb[8];
    #pragma unroll
    for (int j = 0; j < 8; j++) bb[j] = bias[n0 + j];
    #pragma unroll
    for (int i = 0; i < 8; i++) {
        float4 v0 = make_float4(acc[i][0]+bb[0], acc[i][1]+bb[1],
                                acc[i][2]+bb[2], acc[i][3]+bb[3]);
        float4 v1 = make_float4(acc[i][4]+bb[4], acc[i][5]+bb[5],
                                acc[i][6]+bb[6], acc[i][7]+bb[7]);
        *(float4*)(&C[(size_t)(m0+i)*N + n0])     = v0;
        *(float4*)(&C[(size_t)(m0+i)*N + n0 + 4]) = v1;
    }
}

// ---------------------------------------------------------------------------
// Flash attention, one CTA per (64-q tile, head, batch). 256 threads.
// Q,K stored d-major [64d][LDT]; V k-major [64k][LDT]; P reuses K buffer.
// Thread (tx,ty) owns q rows ty*4+i, and k/d cols tx*4+j. fp32 throughout.
// ---------------------------------------------------------------------------
__global__ __launch_bounds__(256) void attn_kernel(
    const float* __restrict__ qkv, float* __restrict__ ctx)
{
    extern __shared__ float sm[];
    float* Qt   = sm;                 // [64][LDT]  Qt[d*LDT + q] (prescaled by 1/8)
    float* KtPs = sm + 64 * LDT;      // K tile [d][k], then P tile [q][k]
    float* Vs   = sm + 2 * 64 * LDT;  // [k][d]
    float* sB   = sm + 3 * 64 * LDT;  // 65-entry bias LUT

    int t  = threadIdx.x;
    int tx = t & 15, ty = t >> 4;
    int q0 = blockIdx.x * 64;
    int h  = blockIdx.y;
    int b  = blockIdx.z;

    const float* base = qkv + (size_t)b * SEQ * QKV_LD + h * HD;

    if (t < 65) sB[t] = g_bias[t];

    #pragma unroll
    for (int r = 0; r < 16; r++) {
        int idx = r * 256 + t;
        int q = idx >> 6, d = idx & 63;
        Qt[d * LDT + q] = base[(size_t)(q0 + q) * QKV_LD + d] * 0.125f;
    }

    float m_s[4], l_s[4], o[4][4];
    #pragma unroll
    for (int i = 0; i < 4; i++) {
        m_s[i] = -1e30f; l_s[i] = 0.f;
        #pragma unroll
        for (int j = 0; j < 4; j++) o[i][j] = 0.f;
    }

    for (int j0 = 0; j0 < SEQ; j0 += 64) {
        __syncthreads();  // previous iter's P/V reads complete
        #pragma unroll
        for (int r = 0; r < 16; r++) {
            int idx = r * 256 + t;
            int k = idx >> 6, d = idx & 63;
            const float* row = base + (size_t)(j0 + k) * QKV_LD;
            KtPs[d * LDT + k] = row[EMB + d];         // K, d-major
            Vs[k * LDT + d]   = row[2 * EMB + d];     // V, k-major
        }
        __syncthreads();

        // S = (Q/8) @ K^T   via rank-1 updates, vectorized along q/k
        float acc[4][4];
        #pragma unroll
        for (int i = 0; i < 4; i++)
            #pragma unroll
            for (int j = 0; j < 4; j++) acc[i][j] = 0.f;

        #pragma unroll 8
        for (int d = 0; d < 64; d++) {
            float4 qv = *(const float4*)(&Qt[d * LDT + ty * 4]);
            float4 kv = *(const float4*)(&KtPs[d * LDT + tx * 4]);
            float qa[4] = {qv.x, qv.y, qv.z, qv.w};
            float ka[4] = {kv.x, kv.y, kv.z, kv.w};
            #pragma unroll
            for (int i = 0; i < 4; i++)
                #pragma unroll
                for (int j = 0; j < 4; j++)
                    acc[i][j] = fmaf(qa[i], ka[j], acc[i][j]);
        }
        __syncthreads();  // everyone done reading K tile (buffer becomes P)

        // bias add + online softmax update; write P into KtPs
        #pragma unroll
        for (int i = 0; i < 4; i++) {
            int qi = q0 + ty * 4 + i;
            #pragma unroll
            for (int j = 0; j < 4; j++) {
                int rel = qi - (j0 + tx * 4 + j);
                rel = rel < -32 ? -32 : (rel > 32 ? 32 : rel);
                acc[i][j] += sB[rel + 32];
            }
            float mt = fmaxf(fmaxf(acc[i][0], acc[i][1]),
                             fmaxf(acc[i][2], acc[i][3]));
            #pragma unroll
            for (int off = 8; off > 0; off >>= 1)
                mt = fmaxf(mt, __shfl_xor_sync(0xffffffffu, mt, off));
            float mnew  = fmaxf(m_s[i], mt);
            float alpha = __expf(m_s[i] - mnew);
            m_s[i] = mnew;
            float lsum = 0.f;
            #pragma unroll
            for (int j = 0; j < 4; j++) {
                acc[i][j] = __expf(acc[i][j] - mnew);
                lsum += acc[i][j];
            }
            #pragma unroll
            for (int off = 8; off > 0; off >>= 1)
                lsum += __shfl_xor_sync(0xffffffffu, lsum, off);
            l_s[i] = l_s[i] * alpha + lsum;
            #pragma unroll
            for (int j = 0; j < 4; j++) o[i][j] *= alpha;
            *(float4*)(&KtPs[(ty * 4 + i) * LDT + tx * 4]) =
                make_float4(acc[i][0], acc[i][1], acc[i][2], acc[i][3]);
        }
        __syncthreads();

        // O += P @ V
        #pragma unroll 4
        for (int kk = 0; kk < 64; kk += 4) {
            float4 vv0 = *(const float4*)(&Vs[(kk + 0) * LDT + tx * 4]);
            float4 vv1 = *(const float4*)(&Vs[(kk + 1) * LDT + tx * 4]);
            float4 vv2 = *(const float4*)(&Vs[(kk + 2) * LDT + tx * 4]);
            float4 vv3 = *(const float4*)(&Vs[(kk + 3) * LDT + tx * 4]);
            #pragma unroll
            for (int i = 0; i < 4; i++) {
                float4 pv = *(const float4*)(&KtPs[(ty * 4 + i) * LDT + kk]);
                o[i][0] = fmaf(pv.x, vv0.x, fmaf(pv.y, vv1.x, fmaf(pv.z, vv2.x, fmaf(pv.w, vv3.x, o[i][0]))));
                o[i][1] = fmaf(pv.x, vv0.y, fmaf(pv.y, vv1.y, fmaf(pv.z, vv2.y, fmaf(pv.w, vv3.y, o[i][1]))));
                o[i][2] = fmaf(pv.x, vv0.z, fmaf(pv.y, vv1.z, fmaf(pv.z, vv2.z, fmaf(pv.w, vv3.z, o[i][2]))));
                o[i][3] = fmaf(pv.x, vv0.w, fmaf(pv.y, vv1.w, fmaf(pv.z, vv2.w, fmaf(pv.w, vv3.w, o[i][3]))));
            }
        }
    }

    float* out = ctx + (size_t)(b * SEQ + q0) * EMB + h * HD;
    #pragma unroll
    for (int i = 0; i < 4; i++) {
        float inv = 1.0f / l_s[i];
        *(float4*)(&out[(size_t)(ty * 4 + i) * EMB + tx * 4]) =
            make_float4(o[i][0]*inv, o[i][1]*inv, o[i][2]*inv, o[i][3]*inv);
    }
}

// ---------------------------------------------------------------------------
extern "C" void kernel_launch(void* const* d_in, const int* in_sizes, int n_in,
                              void* d_out, int out_size)
{
    const float* x  = (const float*)d_in[0];
    const float* w1 = (const float*)d_in[1];
    const float* b1 = (const float*)d_in[2];
    const float* w2 = (const float*)d_in[3];
    const float* b2 = (const float*)d_in[4];
    const float* rb = (const float*)d_in[5];
    float* out = (float*)d_out;

    float* qkv_p; cudaGetSymbolAddress((void**)&qkv_p, g_qkv);
    float* ctx_p; cudaGetSymbolAddress((void**)&ctx_p, g_ctx);

    bias_kernel<<<1, 96>>>(rb);

    dim3 g1(3 * EMB / 128, (BATCH * SEQ) / 128);
    gemm_nt<<<g1, 256>>>(x, w1, b1, qkv_p, BATCH * SEQ, 3 * EMB, EMB);

    size_t shm = (size_t)(3 * 64 * LDT + 68) * sizeof(float);
    cudaFuncSetAttribute(attn_kernel,
                         cudaFuncAttributeMaxDynamicSharedMemorySize, (int)shm);
    dim3 g2(SEQ / 64, NH, BATCH);
    attn_kernel<<<g2, 256, shm>>>(qkv_p, ctx_p);

    dim3 g3(EMB / 128, (BATCH * SEQ) / 128);
    gemm_nt<<<g3, 256>>>(ctx_p, w2, b2, out, BATCH * SEQ, EMB, EMB);
}

// round 3
// speedup vs baseline: 1.3550x; 1.3550x over previous
#include <cuda_runtime.h>
#include <cuda_bf16.h>
#include <math.h>
#include <stdint.h>

#define BATCH 4
#define SEQ   2048
#define EMB   1024
#define NH    16
#define HD    64
#define QKV_LD (3*EMB)
#define LDT   68

// ---------------- scratch (__device__ globals; no allocs allowed) ----------
__device__ float g_qkv[(size_t)BATCH * SEQ * 3 * EMB];
__device__ float g_ctx[(size_t)BATCH * SEQ * EMB];
__device__ float g_bias[65];
__device__ __nv_bfloat16 g_ah[(size_t)BATCH * SEQ * EMB];   // A hi (activations)
__device__ __nv_bfloat16 g_al[(size_t)BATCH * SEQ * EMB];   // A lo
__device__ __nv_bfloat16 g_bh[(size_t)3 * EMB * EMB];       // B hi (weights)
__device__ __nv_bfloat16 g_bl[(size_t)3 * EMB * EMB];       // B lo

// ---------------- PTX helpers (sm_80-era only: valid on compute_103) -------
__device__ __forceinline__ uint32_t smem_u32(const void* p) {
    uint32_t a;
    asm("{ .reg .u64 t; cvta.to.shared.u64 t, %1; cvt.u32.u64 %0, t; }" : "=r"(a) : "l"(p));
    return a;
}
#define CP16(d, s)   asm volatile("cp.async.cg.shared.global [%0], [%1], 16;" :: "r"(d), "l"(s))
#define CP_COMMIT()  asm volatile("cp.async.commit_group;" ::: "memory")
#define CP_WAIT1()   asm volatile("cp.async.wait_group 1;" ::: "memory")
#define CP_WAIT0()   asm volatile("cp.async.wait_group 0;" ::: "memory")

#define LDSM4(r0, r1, r2, r3, a) \
    asm volatile("ldmatrix.sync.aligned.m8n8.x4.shared.b16 {%0,%1,%2,%3}, [%4];" \
        : "=r"(r0), "=r"(r1), "=r"(r2), "=r"(r3) : "r"(a))

#define MMA16816(d, a, b) \
    asm volatile("mma.sync.aligned.m16n8k16.row.col.f32.bf16.bf16.f32 " \
        "{%0,%1,%2,%3}, {%4,%5,%6,%7}, {%8,%9}, {%0,%1,%2,%3};" \
        : "+f"((d)[0]), "+f"((d)[1]), "+f"((d)[2]), "+f"((d)[3]) \
        : "r"((a)[0]), "r"((a)[1]), "r"((a)[2]), "r"((a)[3]), "r"((b)[0]), "r"((b)[1]))

// ---------------------------------------------------------------------------
// bias LUT
// ---------------------------------------------------------------------------
__global__ void bias_kernel(const float* __restrict__ rel_bias) {
    int r = threadIdx.x;
    if (r < 65) {
        float s = 0.f;
        #pragma unroll
        for (int h = 0; h < NH; h++) s += rel_bias[r * NH + h];
        g_bias[r] = s * (1.0f / NH);
    }
}

// ---------------------------------------------------------------------------
// split fp32 -> bf16 hi + bf16 lo
// ---------------------------------------------------------------------------
__global__ __launch_bounds__(256) void split_kernel(
    const float* __restrict__ x, __nv_bfloat16* __restrict__ hi,
    __nv_bfloat16* __restrict__ lo, int n4)
{
    int i = blockIdx.x * blockDim.x + threadIdx.x;
    if (i >= n4) return;
    float4 v = ((const float4*)x)[i];
    __nv_bfloat16 h0 = __float2bfloat16(v.x), h1 = __float2bfloat16(v.y);
    __nv_bfloat16 h2 = __float2bfloat16(v.z), h3 = __float2bfloat16(v.w);
    __nv_bfloat162 H0 = {h0, h1}, H1 = {h2, h3};
    __nv_bfloat162 L0 = {__float2bfloat16(v.x - __bfloat162float(h0)),
                         __float2bfloat16(v.y - __bfloat162float(h1))};
    __nv_bfloat162 L1 = {__float2bfloat16(v.z - __bfloat162float(h2)),
                         __float2bfloat16(v.w - __bfloat162float(h3))};
    ((__nv_bfloat162*)hi)[i*2]   = H0;  ((__nv_bfloat162*)hi)[i*2+1] = H1;
    ((__nv_bfloat162*)lo)[i*2]   = L0;  ((__nv_bfloat162*)lo)[i*2+1] = L1;
}

// ---------------------------------------------------------------------------
// HMMA split-bf16 GEMM:  C[M,N] = (Ah+Al)[M,K] @ (Bh+Bl)[N,K]^T + bias[N]
// 128x128 CTA tile, BK=32, 512 threads (16 warps, 32x32 warp tile),
// cp.async double-buffered. SMEM rows padded to 80B (conflict-free ldmatrix).
// ---------------------------------------------------------------------------
#define TIL 10240              // one 128x32 bf16 tile, rows padded to 80B
#define STG (4*TIL)            // stage: Ah, Al, Bh, Bl

__global__ __launch_bounds__(512) void gemm_hmma(
    const __nv_bfloat16* __restrict__ Ah, const __nv_bfloat16* __restrict__ Al,
    const __nv_bfloat16* __restrict__ Bh, const __nv_bfloat16* __restrict__ Bl,
    const float* __restrict__ bias, float* __restrict__ C,
    int M, int N, int K)
{
    extern __shared__ char sm[];
    uint32_t smb = smem_u32(sm);
    const int t = threadIdx.x;
    const int lane = t & 31, wid = t >> 5;
    const int wm = wid >> 2, wn = wid & 3;       // 4x4 warp grid, 32x32 tiles
    const int m0 = blockIdx.y * 128, n0 = blockIdx.x * 128;

    // copy coords: 512 chunks of 16B per tile, one per thread
    const int crow = t >> 2, cch = t & 3;
    const size_t aoff0 = (size_t)(m0 + crow) * K + cch * 8;
    const size_t boff0 = (size_t)(n0 + crow) * K + cch * 8;
    const uint32_t doff0 = (uint32_t)(crow * 80 + cch * 16);

    auto load_stage = [&](int buf, int k0) {
        uint32_t d = smb + buf * STG + doff0;
        CP16(d,           Ah + aoff0 + k0);
        CP16(d + TIL,     Al + aoff0 + k0);
        CP16(d + 2*TIL,   Bh + boff0 + k0);
        CP16(d + 3*TIL,   Bl + boff0 + k0);
    };

    float acc[2][4][4];
    #pragma unroll
    for (int i = 0; i < 2; i++)
        #pragma unroll
        for (int j = 0; j < 4; j++)
            #pragma unroll
            for (int v = 0; v < 4; v++) acc[i][j][v] = 0.f;

    const int NS = K >> 5;
    load_stage(0, 0);
    CP_COMMIT();

    for (int s = 0; s < NS; s++) {
        if (s + 1 < NS) { load_stage((s + 1) & 1, (s + 1) << 5); CP_COMMIT(); CP_WAIT1(); }
        else           { CP_WAIT0(); }
        __syncthreads();

        uint32_t abase = smb + (s & 1) * STG;       // Ah
        uint32_t bbase = abase + 2 * TIL;           // Bh

        #pragma unroll
        for (int ks = 0; ks < 2; ks++) {
            const int kc = ks * 16;
            // ldmatrix addresses
            uint32_t a_ad[2], b_ad[2];
            #pragma unroll
            for (int mt = 0; mt < 2; mt++)
                a_ad[mt] = abase + (uint32_t)((wm*32 + mt*16 + (lane & 15)) * 80
                                              + (kc + (lane >> 4) * 8) * 2);
            #pragma unroll
            for (int p = 0; p < 2; p++)
                b_ad[p] = bbase + (uint32_t)((wn*32 + p*16 + (lane >> 4) * 8 + (lane & 7)) * 80
                                             + (kc + ((lane >> 3) & 1) * 8) * 2);

            uint32_t af[2][4], alf[2][4], bf[4][2];
            LDSM4(af[0][0], af[0][1], af[0][2], af[0][3], a_ad[0]);
            LDSM4(af[1][0], af[1][1], af[1][2], af[1][3], a_ad[1]);
            LDSM4(bf[0][0], bf[0][1], bf[1][0], bf[1][1], b_ad[0]);
            LDSM4(bf[2][0], bf[2][1], bf[3][0], bf[3][1], b_ad[1]);
            // HH
            #pragma unroll
            for (int mt = 0; mt < 2; mt++)
                #pragma unroll
                for (int nt = 0; nt < 4; nt++) MMA16816(acc[mt][nt], af[mt], bf[nt]);
            // LH (Al x Bh) — Bh still live
            LDSM4(alf[0][0], alf[0][1], alf[0][2], alf[0][3], a_ad[0] + TIL);
            LDSM4(alf[1][0], alf[1][1], alf[1][2], alf[1][3], a_ad[1] + TIL);
            #pragma unroll
            for (int mt = 0; mt < 2; mt++)
                #pragma unroll
                for (int nt = 0; nt < 4; nt++) MMA16816(acc[mt][nt], alf[mt], bf[nt]);
            // HL (Ah x Bl) — overwrite bf with Bl
            LDSM4(bf[0][0], bf[0][1], bf[1][0], bf[1][1], b_ad[0] + TIL);
            LDSM4(bf[2][0], bf[2][1], bf[3][0], bf[3][1], b_ad[1] + TIL);
            #pragma unroll
            for (int mt = 0; mt < 2; mt++)
                #pragma unroll
                for (int nt = 0; nt < 4; nt++) MMA16816(acc[mt][nt], af[mt], bf[nt]);
        }
        __syncthreads();
    }

    // epilogue: d0,d1 -> (m, n..n+1), d2,d3 -> (m+8, n..n+1)
    #pragma unroll
    for (int mt = 0; mt < 2; mt++) {
        int m = m0 + wm*32 + mt*16 + (lane >> 2);
        #pragma unroll
        for (int nt = 0; nt < 4; nt++) {
            int n = n0 + wn*32 + nt*8 + (lane & 3) * 2;
            float b0 = bias[n], b1 = bias[n + 1];
            float2 v0 = make_float2(acc[mt][nt][0] + b0, acc[mt][nt][1] + b1);
            float2 v1 = make_float2(acc[mt][nt][2] + b0, acc[mt][nt][3] + b1);
            *(float2*)(&C[(size_t)m * N + n])       = v0;
            *(float2*)(&C[(size_t)(m + 8) * N + n]) = v1;
        }
    }
}

// ---------------------------------------------------------------------------
// Flash attention (R1 version): one CTA per (64-q tile, head, batch)
// ---------------------------------------------------------------------------
__global__ __launch_bounds__(256) void attn_kernel(
    const float* __restrict__ qkv, float* __restrict__ ctx)
{
    extern __shared__ float smf[];
    float* Qt   = smf;
    float* KtPs = smf + 64 * LDT;
    float* Vs   = smf + 2 * 64 * LDT;
    float* sB   = smf + 3 * 64 * LDT;

    int t  = threadIdx.x;
    int tx = t & 15, ty = t >> 4;
    int q0 = blockIdx.x * 64;
    int h  = blockIdx.y;
    int b  = blockIdx.z;

    const float* base = qkv + (size_t)b * SEQ * QKV_LD + h * HD;

    if (t < 65) sB[t] = g_bias[t];

    #pragma unroll
    for (int r = 0; r < 16; r++) {
        int idx = r * 256 + t;
        int q = idx >> 6, d = idx & 63;
        Qt[d * LDT + q] = base[(size_t)(q0 + q) * QKV_LD + d] * 0.125f;
    }

    float m_s[4], l_s[4], o[4][4];
    #pragma unroll
    for (int i = 0; i < 4; i++) {
        m_s[i] = -1e30f; l_s[i] = 0.f;
        #pragma unroll
        for (int j = 0; j < 4; j++) o[i][j] = 0.f;
    }

    for (int j0 = 0; j0 < SEQ; j0 += 64) {
        __syncthreads();
        #pragma unroll
        for (int r = 0; r < 16; r++) {
            int idx = r * 256 + t;
            int k = idx >> 6, d = idx & 63;
            const float* row = base + (size_t)(j0 + k) * QKV_LD;
            KtPs[d * LDT + k] = row[EMB + d];
            Vs[k * LDT + d]   = row[2 * EMB + d];
        }
        __syncthreads();

        float acc[4][4];
        #pragma unroll
        for (int i = 0; i < 4; i++)
            #pragma unroll
            for (int j = 0; j < 4; j++) acc[i][j] = 0.f;

        #pragma unroll 8
        for (int d = 0; d < 64; d++) {
            float4 qv = *(const float4*)(&Qt[d * LDT + ty * 4]);
            float4 kv = *(const float4*)(&KtPs[d * LDT + tx * 4]);
            float qa[4] = {qv.x, qv.y, qv.z, qv.w};
            float ka[4] = {kv.x, kv.y, kv.z, kv.w};
            #pragma unroll
            for (int i = 0; i < 4; i++)
                #pragma unroll
                for (int j = 0; j < 4; j++)
                    acc[i][j] = fmaf(qa[i], ka[j], acc[i][j]);
        }
        __syncthreads();

        #pragma unroll
        for (int i = 0; i < 4; i++) {
            int qi = q0 + ty * 4 + i;
            #pragma unroll
            for (int j = 0; j < 4; j++) {
                int rel = qi - (j0 + tx * 4 + j);
                rel = rel < -32 ? -32 : (rel > 32 ? 32 : rel);
                acc[i][j] += sB[rel + 32];
            }
            float mt = fmaxf(fmaxf(acc[i][0], acc[i][1]),
                             fmaxf(acc[i][2], acc[i][3]));
            #pragma unroll
            for (int off = 8; off > 0; off >>= 1)
                mt = fmaxf(mt, __shfl_xor_sync(0xffffffffu, mt, off));
            float mnew  = fmaxf(m_s[i], mt);
            float alpha = __expf(m_s[i] - mnew);
            m_s[i] = mnew;
            float lsum = 0.f;
            #pragma unroll
            for (int j = 0; j < 4; j++) {
                acc[i][j] = __expf(acc[i][j] - mnew);
                lsum += acc[i][j];
            }
            #pragma unroll
            for (int off = 8; off > 0; off >>= 1)
                lsum += __shfl_xor_sync(0xffffffffu, lsum, off);
            l_s[i] = l_s[i] * alpha + lsum;
            #pragma unroll
            for (int j = 0; j < 4; j++) o[i][j] *= alpha;
            *(float4*)(&KtPs[(ty * 4 + i) * LDT + tx * 4]) =
                make_float4(acc[i][0], acc[i][1], acc[i][2], acc[i][3]);
        }
        __syncthreads();

        #pragma unroll 4
        for (int kk = 0; kk < 64; kk += 4) {
            float4 vv0 = *(const float4*)(&Vs[(kk + 0) * LDT + tx * 4]);
            float4 vv1 = *(const float4*)(&Vs[(kk + 1) * LDT + tx * 4]);
            float4 vv2 = *(const float4*)(&Vs[(kk + 2) * LDT + tx * 4]);
            float4 vv3 = *(const float4*)(&Vs[(kk + 3) * LDT + tx * 4]);
            #pragma unroll
            for (int i = 0; i < 4; i++) {
                float4 pv = *(const float4*)(&KtPs[(ty * 4 + i) * LDT + kk]);
                o[i][0] = fmaf(pv.x, vv0.x, fmaf(pv.y, vv1.x, fmaf(pv.z, vv2.x, fmaf(pv.w, vv3.x, o[i][0]))));
                o[i][1] = fmaf(pv.x, vv0.y, fmaf(pv.y, vv1.y, fmaf(pv.z, vv2.y, fmaf(pv.w, vv3.y, o[i][1]))));
                o[i][2] = fmaf(pv.x, vv0.z, fmaf(pv.y, vv1.z, fmaf(pv.z, vv2.z, fmaf(pv.w, vv3.z, o[i][2]))));
                o[i][3] = fmaf(pv.x, vv0.w, fmaf(pv.y, vv1.w, fmaf(pv.z, vv2.w, fmaf(pv.w, vv3.w, o[i][3]))));
            }
        }
    }

    float* out = ctx + (size_t)(b * SEQ + q0) * EMB + h * HD;
    #pragma unroll
    for (int i = 0; i < 4; i++) {
        float inv = 1.0f / l_s[i];
        *(float4*)(&out[(size_t)(ty * 4 + i) * EMB + tx * 4]) =
            make_float4(o[i][0]*inv, o[i][1]*inv, o[i][2]*inv, o[i][3]*inv);
    }
}

// ---------------------------------------------------------------------------
extern "C" void kernel_launch(void* const* d_in, const int* in_sizes, int n_in,
                              void* d_out, int out_size)
{
    const float* x  = (const float*)d_in[0];
    const float* w1 = (const float*)d_in[1];
    const float* b1 = (const float*)d_in[2];
    const float* w2 = (const float*)d_in[3];
    const float* b2 = (const float*)d_in[4];
    const float* rb = (const float*)d_in[5];
    float* out = (float*)d_out;

    float* qkv_p; cudaGetSymbolAddress((void**)&qkv_p, g_qkv);
    float* ctx_p; cudaGetSymbolAddress((void**)&ctx_p, g_ctx);
    __nv_bfloat16 *ah, *al, *bh, *bl;
    cudaGetSymbolAddress((void**)&ah, g_ah);
    cudaGetSymbolAddress((void**)&al, g_al);
    cudaGetSymbolAddress((void**)&bh, g_bh);
    cudaGetSymbolAddress((void**)&bl, g_bl);

    const int MM = BATCH * SEQ;            // 8192
    const size_t gemm_shm = 2 * (size_t)STG;   // 81920 B
    cudaFuncSetAttribute(gemm_hmma, cudaFuncAttributeMaxDynamicSharedMemorySize,
                         (int)gemm_shm);

    bias_kernel<<<1, 96>>>(rb);

    // split x and w1
    {
        int n4 = MM * EMB / 4;
        split_kernel<<<(n4 + 255) / 256, 256>>>(x, ah, al, n4);
        n4 = 3 * EMB * EMB / 4;
        split_kernel<<<(n4 + 255) / 256, 256>>>(w1, bh, bl, n4);
    }
    // QKV projection
    {
        dim3 g(3 * EMB / 128, MM / 128);
        gemm_hmma<<<g, 512, gemm_shm>>>(ah, al, bh, bl, b1, qkv_p,
                                        MM, 3 * EMB, EMB);
    }
    // attention
    {
        size_t shm = (size_t)(3 * 64 * LDT + 68) * sizeof(float);
        cudaFuncSetAttribute(attn_kernel,
                             cudaFuncAttributeMaxDynamicSharedMemorySize, (int)shm);
        dim3 g(SEQ / 64, NH, BATCH);
        attn_kernel<<<g, 256, shm>>>(qkv_p, ctx_p);
    }
    // split ctx and w2, out projection
    {
        int n4 = MM * EMB / 4;
        split_kernel<<<(n4 + 255) / 256, 256>>>(ctx_p, ah, al, n4);
        n4 = EMB * EMB / 4;
        split_kernel<<<(n4 + 255) / 256, 256>>>(w2, bh, bl, n4);
        dim3 g(EMB / 128, MM / 128);
        gemm_hmma<<<g, 512, gemm_shm>>>(ah, al, bh, bl, b2, out,
                                        MM, EMB, EMB);
    }
}

// round 4
// speedup vs baseline: 2.5520x; 1.8833x over previous
#include <cuda_runtime.h>
#include <cuda_bf16.h>
#include <math.h>
#include <stdint.h>

#define BATCH 4
#define SEQ   2048
#define EMB   1024
#define NH    16
#define HD    64
#define QKV_LD (3*EMB)

// ---------------- scratch (__device__ globals; no allocs allowed) ----------
__device__ float g_qkv[(size_t)BATCH * SEQ * 3 * EMB];
__device__ float g_ctx[(size_t)BATCH * SEQ * EMB];
__device__ float g_bias[65];
__device__ __nv_bfloat16 g_ah[(size_t)BATCH * SEQ * EMB];
__device__ __nv_bfloat16 g_al[(size_t)BATCH * SEQ * EMB];
__device__ __nv_bfloat16 g_bh[(size_t)3 * EMB * EMB];
__device__ __nv_bfloat16 g_bl[(size_t)3 * EMB * EMB];
// per-head split attention operands [B, NH, S, D]
#define HSZ ((size_t)BATCH * NH * SEQ * HD)
__device__ __nv_bfloat16 g_qh[HSZ], g_ql[HSZ];
__device__ __nv_bfloat16 g_kh[HSZ], g_kl[HSZ];
__device__ __nv_bfloat16 g_vh[HSZ], g_vl[HSZ];

// ---------------- PTX helpers (sm_80-era only: valid on compute_103) -------
__device__ __forceinline__ uint32_t smem_u32(const void* p) {
    uint32_t a;
    asm("{ .reg .u64 t; cvta.to.shared.u64 t, %1; cvt.u32.u64 %0, t; }" : "=r"(a) : "l"(p));
    return a;
}
#define CP16(d, s)   asm volatile("cp.async.cg.shared.global [%0], [%1], 16;" :: "r"(d), "l"(s))
#define CP_COMMIT()  asm volatile("cp.async.commit_group;" ::: "memory")
#define CP_WAIT1()   asm volatile("cp.async.wait_group 1;" ::: "memory")
#define CP_WAIT0()   asm volatile("cp.async.wait_group 0;" ::: "memory")

#define LDSM4(r0, r1, r2, r3, a) \
    asm volatile("ldmatrix.sync.aligned.m8n8.x4.shared.b16 {%0,%1,%2,%3}, [%4];" \
        : "=r"(r0), "=r"(r1), "=r"(r2), "=r"(r3) : "r"(a))
#define LDSM4T(r0, r1, r2, r3, a) \
    asm volatile("ldmatrix.sync.aligned.m8n8.x4.trans.shared.b16 {%0,%1,%2,%3}, [%4];" \
        : "=r"(r0), "=r"(r1), "=r"(r2), "=r"(r3) : "r"(a))

#define MMA16816(d, a, b) \
    asm volatile("mma.sync.aligned.m16n8k16.row.col.f32.bf16.bf16.f32 " \
        "{%0,%1,%2,%3}, {%4,%5,%6,%7}, {%8,%9}, {%0,%1,%2,%3};" \
        : "+f"((d)[0]), "+f"((d)[1]), "+f"((d)[2]), "+f"((d)[3]) \
        : "r"((a)[0]), "r"((a)[1]), "r"((a)[2]), "r"((a)[3]), "r"((b)[0]), "r"((b)[1]))

// ---------------------------------------------------------------------------
__global__ void bias_kernel(const float* __restrict__ rel_bias) {
    int r = threadIdx.x;
    if (r < 65) {
        float s = 0.f;
        #pragma unroll
        for (int h = 0; h < NH; h++) s += rel_bias[r * NH + h];
        g_bias[r] = s * (1.0f / NH);
    }
}

// ---------------------------------------------------------------------------
__global__ __launch_bounds__(256) void split_kernel(
    const float* __restrict__ x, __nv_bfloat16* __restrict__ hi,
    __nv_bfloat16* __restrict__ lo, int n4)
{
    int i = blockIdx.x * blockDim.x + threadIdx.x;
    if (i >= n4) return;
    float4 v = ((const float4*)x)[i];
    __nv_bfloat16 h0 = __float2bfloat16(v.x), h1 = __float2bfloat16(v.y);
    __nv_bfloat16 h2 = __float2bfloat16(v.z), h3 = __float2bfloat16(v.w);
    __nv_bfloat162 H0 = {h0, h1}, H1 = {h2, h3};
    __nv_bfloat162 L0 = {__float2bfloat16(v.x - __bfloat162float(h0)),
                         __float2bfloat16(v.y - __bfloat162float(h1))};
    __nv_bfloat162 L1 = {__float2bfloat16(v.z - __bfloat162float(h2)),
                         __float2bfloat16(v.w - __bfloat162float(h3))};
    ((__nv_bfloat162*)hi)[i*2]   = H0;  ((__nv_bfloat162*)hi)[i*2+1] = H1;
    ((__nv_bfloat162*)lo)[i*2]   = L0;  ((__nv_bfloat162*)lo)[i*2+1] = L1;
}

// ---------------------------------------------------------------------------
// qkv fp32 [B,S,3E]  ->  per-head split bf16 arrays [B,NH,S,D] (q scaled 1/8)
// ---------------------------------------------------------------------------
__global__ __launch_bounds__(384) void qkv_split(
    const float* __restrict__ qkv,
    __nv_bfloat16* __restrict__ qh, __nv_bfloat16* __restrict__ ql,
    __nv_bfloat16* __restrict__ kh, __nv_bfloat16* __restrict__ kl,
    __nv_bfloat16* __restrict__ vh, __nv_bfloat16* __restrict__ vl)
{
    int blk = blockIdx.x;                 // b*SEQ + s
    int t = threadIdx.x;
    int e0 = t * 8;
    int which = e0 >> 10;
    int h = (e0 & 1023) >> 6;
    int d = e0 & 63;
    const float* src = qkv + (size_t)blk * QKV_LD + e0;
    __nv_bfloat16 *ph, *pl;
    float sc = 1.0f;
    if (which == 0)      { ph = qh; pl = ql; sc = 0.125f; }
    else if (which == 1) { ph = kh; pl = kl; }
    else                 { ph = vh; pl = vl; }
    size_t o = (((size_t)(blk / SEQ) * NH + h) * SEQ + (blk % SEQ)) * HD + d;
    float4 v0 = *(const float4*)src;
    float4 v1 = *(const float4*)(src + 4);
    float vv[8] = {v0.x*sc, v0.y*sc, v0.z*sc, v0.w*sc,
                   v1.x*sc, v1.y*sc, v1.z*sc, v1.w*sc};
    #pragma unroll
    for (int j = 0; j < 4; j++) {
        __nv_bfloat16 a = __float2bfloat16(vv[2*j]);
        __nv_bfloat16 b = __float2bfloat16(vv[2*j+1]);
        __nv_bfloat162 H = {a, b};
        __nv_bfloat162 L = {__float2bfloat16(vv[2*j]   - __bfloat162float(a)),
                            __float2bfloat16(vv[2*j+1] - __bfloat162float(b))};
        *(__nv_bfloat162*)(ph + o + 2*j) = H;
        *(__nv_bfloat162*)(pl + o + 2*j) = L;
    }
}

// ---------------------------------------------------------------------------
// HMMA split-bf16 GEMM (unchanged from R3)
// ---------------------------------------------------------------------------
#define TIL 10240
#define STG (4*TIL)

__global__ __launch_bounds__(512) void gemm_hmma(
    const __nv_bfloat16* __restrict__ Ah, const __nv_bfloat16* __restrict__ Al,
    const __nv_bfloat16* __restrict__ Bh, const __nv_bfloat16* __restrict__ Bl,
    const float* __restrict__ bias, float* __restrict__ C,
    int M, int N, int K)
{
    extern __shared__ char sm[];
    uint32_t smb = smem_u32(sm);
    const int t = threadIdx.x;
    const int lane = t & 31, wid = t >> 5;
    const int wm = wid >> 2, wn = wid & 3;
    const int m0 = blockIdx.y * 128, n0 = blockIdx.x * 128;

    const int crow = t >> 2, cch = t & 3;
    const size_t aoff0 = (size_t)(m0 + crow) * K + cch * 8;
    const size_t boff0 = (size_t)(n0 + crow) * K + cch * 8;
    const uint32_t doff0 = (uint32_t)(crow * 80 + cch * 16);

    auto load_stage = [&](int buf, int k0) {
        uint32_t d = smb + buf * STG + doff0;
        CP16(d,           Ah + aoff0 + k0);
        CP16(d + TIL,     Al + aoff0 + k0);
        CP16(d + 2*TIL,   Bh + boff0 + k0);
        CP16(d + 3*TIL,   Bl + boff0 + k0);
    };

    float acc[2][4][4];
    #pragma unroll
    for (int i = 0; i < 2; i++)
        #pragma unroll
        for (int j = 0; j < 4; j++)
            #pragma unroll
            for (int v = 0; v < 4; v++) acc[i][j][v] = 0.f;

    const int NS = K >> 5;
    load_stage(0, 0);
    CP_COMMIT();

    for (int s = 0; s < NS; s++) {
        if (s + 1 < NS) { load_stage((s + 1) & 1, (s + 1) << 5); CP_COMMIT(); CP_WAIT1(); }
        else           { CP_WAIT0(); }
        __syncthreads();

        uint32_t abase = smb + (s & 1) * STG;
        uint32_t bbase = abase + 2 * TIL;

        #pragma unroll
        for (int ks = 0; ks < 2; ks++) {
            const int kc = ks * 16;
            uint32_t a_ad[2], b_ad[2];
            #pragma unroll
            for (int mt = 0; mt < 2; mt++)
                a_ad[mt] = abase + (uint32_t)((wm*32 + mt*16 + (lane & 15)) * 80
                                              + (kc + (lane >> 4) * 8) * 2);
            #pragma unroll
            for (int p = 0; p < 2; p++)
                b_ad[p] = bbase + (uint32_t)((wn*32 + p*16 + (lane >> 4) * 8 + (lane & 7)) * 80
                                             + (kc + ((lane >> 3) & 1) * 8) * 2);

            uint32_t af[2][4], alf[2][4], bf[4][2];
            LDSM4(af[0][0], af[0][1], af[0][2], af[0][3], a_ad[0]);
            LDSM4(af[1][0], af[1][1], af[1][2], af[1][3], a_ad[1]);
            LDSM4(bf[0][0], bf[0][1], bf[1][0], bf[1][1], b_ad[0]);
            LDSM4(bf[2][0], bf[2][1], bf[3][0], bf[3][1], b_ad[1]);
            #pragma unroll
            for (int mt = 0; mt < 2; mt++)
                #pragma unroll
                for (int nt = 0; nt < 4; nt++) MMA16816(acc[mt][nt], af[mt], bf[nt]);
            LDSM4(alf[0][0], alf[0][1], alf[0][2], alf[0][3], a_ad[0] + TIL);
            LDSM4(alf[1][0], alf[1][1], alf[1][2], alf[1][3], a_ad[1] + TIL);
            #pragma unroll
            for (int mt = 0; mt < 2; mt++)
                #pragma unroll
                for (int nt = 0; nt < 4; nt++) MMA16816(acc[mt][nt], alf[mt], bf[nt]);
            LDSM4(bf[0][0], bf[0][1], bf[1][0], bf[1][1], b_ad[0] + TIL);
            LDSM4(bf[2][0], bf[2][1], bf[3][0], bf[3][1], b_ad[1] + TIL);
            #pragma unroll
            for (int mt = 0; mt < 2; mt++)
                #pragma unroll
                for (int nt = 0; nt < 4; nt++) MMA16816(acc[mt][nt], af[mt], bf[nt]);
        }
        __syncthreads();
    }

    #pragma unroll
    for (int mt = 0; mt < 2; mt++) {
        int m = m0 + wm*32 + mt*16 + (lane >> 2);
        #pragma unroll
        for (int nt = 0; nt < 4; nt++) {
            int n = n0 + wn*32 + nt*8 + (lane & 3) * 2;
            float b0 = bias[n], b1 = bias[n + 1];
            float2 v0 = make_float2(acc[mt][nt][0] + b0, acc[mt][nt][1] + b1);
            float2 v1 = make_float2(acc[mt][nt][2] + b0, acc[mt][nt][3] + b1);
            *(float2*)(&C[(size_t)m * N + n])       = v0;
            *(float2*)(&C[(size_t)(m + 8) * N + n]) = v1;
        }
    }
}

// ---------------------------------------------------------------------------
// HMMA flash attention. CTA = (128 q rows, head, batch); 8 warps (m16 each).
// KV tile 64. Smem rows padded to 144B. Split-bf16 everywhere (3-term MMA).
// ---------------------------------------------------------------------------
#define AQH 0u
#define AQL 18432u
#define AST 36864u          // stage base
#define ASS 36864u          // stage size (Kh,Kl,Vh,Vl @ 9216 each)
#define ALUT 110592u
#define ASMEM 110912u

__device__ __forceinline__ uint32_t packres(float a, float b, float& ra, float& rb) {
    __nv_bfloat162 h;
    h.x = __float2bfloat16(a); h.y = __float2bfloat16(b);
    ra = a - __bfloat162float(h.x);
    rb = b - __bfloat162float(h.y);
    return *(uint32_t*)&h;
}
__device__ __forceinline__ uint32_t packbf(float a, float b) {
    __nv_bfloat162 h;
    h.x = __float2bfloat16(a); h.y = __float2bfloat16(b);
    return *(uint32_t*)&h;
}

__global__ __launch_bounds__(256) void attn_hmma(
    const __nv_bfloat16* __restrict__ qh_g, const __nv_bfloat16* __restrict__ ql_g,
    const __nv_bfloat16* __restrict__ kh_g, const __nv_bfloat16* __restrict__ kl_g,
    const __nv_bfloat16* __restrict__ vh_g, const __nv_bfloat16* __restrict__ vl_g,
    float* __restrict__ ctx)
{
    extern __shared__ char sm[];
    uint32_t smb = smem_u32(sm);
    const int t = threadIdx.x, lane = t & 31, wq = t >> 5;
    const int q0 = blockIdx.x * 128, h = blockIdx.y, b = blockIdx.z;

    float* lut = (float*)(sm + ALUT);
    if (t < 65) lut[t] = g_bias[t];

    const size_t hb = ((size_t)b * NH + h) * SEQ;
    const size_t qg = (hb + q0) * HD;

    // Q: 2 arrays x 1024 16B chunks
    #pragma unroll
    for (int i = 0; i < 4; i++) {
        int id = t * 4 + i, row = id >> 3, ch = id & 7;
        uint32_t so = (uint32_t)(row * 144 + ch * 16);
        size_t go = qg + (size_t)row * 64 + ch * 8;
        CP16(smb + AQH + so, qh_g + go);
        CP16(smb + AQL + so, ql_g + go);
    }
    auto load_kv = [&](int buf, int j0) {
        uint32_t sb = smb + AST + (uint32_t)buf * ASS;
        size_t gb = (hb + j0) * HD;
        #pragma unroll
        for (int i = 0; i < 2; i++) {
            int id = t * 2 + i, row = id >> 3, ch = id & 7;
            uint32_t so = (uint32_t)(row * 144 + ch * 16);
            size_t go = gb + (size_t)row * 64 + ch * 8;
            CP16(sb + so,         kh_g + go);
            CP16(sb + 9216 + so,  kl_g + go);
            CP16(sb + 18432 + so, vh_g + go);
            CP16(sb + 27648 + so, vl_g + go);
        }
    };
    load_kv(0, 0);
    CP_COMMIT();

    uint32_t qhf[4][4], qlf[4][4];
    float oacc[8][4];
    #pragma unroll
    for (int i = 0; i < 8; i++)
        #pragma unroll
        for (int j = 0; j < 4; j++) oacc[i][j] = 0.f;
    float mrow0 = -1e30f, mrow1 = -1e30f, lrow0 = 0.f, lrow1 = 0.f;

    const int qr0 = q0 + wq * 16 + (lane >> 2);
    const int NT = SEQ / 64;

    for (int jt = 0; jt < NT; jt++) {
        if (jt + 1 < NT) { load_kv((jt + 1) & 1, (jt + 1) * 64); CP_COMMIT(); CP_WAIT1(); }
        else            { CP_WAIT0(); }
        __syncthreads();

        if (jt == 0) {
            #pragma unroll
            for (int ks = 0; ks < 4; ks++) {
                uint32_t ar = (uint32_t)((wq*16 + ((lane>>3)&1)*8 + (lane&7)) * 144
                                         + ks*32 + ((lane>>4)&1)*16);
                LDSM4(qhf[ks][0], qhf[ks][1], qhf[ks][2], qhf[ks][3], smb + AQH + ar);
                LDSM4(qlf[ks][0], qlf[ks][1], qlf[ks][2], qlf[ks][3], smb + AQL + ar);
            }
        }

        uint32_t sb = smb + AST + (uint32_t)(jt & 1) * ASS;
        float sacc[8][4];
        #pragma unroll
        for (int i = 0; i < 8; i++)
            #pragma unroll
            for (int j = 0; j < 4; j++) sacc[i][j] = 0.f;

        // S = Qh*Kh + Ql*Kh + Qh*Kl
        #pragma unroll
        for (int ks = 0; ks < 4; ks++) {
            #pragma unroll
            for (int p = 0; p < 4; p++) {
                uint32_t kr = (uint32_t)((p*16 + ((lane>>4)&1)*8 + (lane&7)) * 144
                                         + ks*32 + ((lane>>3)&1)*16);
                uint32_t h0, h1, h2, h3, l0, l1, l2, l3;
                LDSM4(h0, h1, h2, h3, sb + kr);
                LDSM4(l0, l1, l2, l3, sb + 9216 + kr);
                uint32_t bh0[2] = {h0, h1}, bh1[2] = {h2, h3};
                uint32_t bl0[2] = {l0, l1}, bl1[2] = {l2, l3};
                MMA16816(sacc[2*p],   qhf[ks], bh0);
                MMA16816(sacc[2*p],   qlf[ks], bh0);
                MMA16816(sacc[2*p],   qhf[ks], bl0);
                MMA16816(sacc[2*p+1], qhf[ks], bh1);
                MMA16816(sacc[2*p+1], qlf[ks], bh1);
                MMA16816(sacc[2*p+1], qhf[ks], bl1);
            }
        }

        // bias + online softmax
        float mx0 = -1e30f, mx1 = -1e30f;
        #pragma unroll
        for (int nt = 0; nt < 8; nt++) {
            #pragma unroll
            for (int j = 0; j < 2; j++) {
                int k = jt * 64 + nt * 8 + (lane & 3) * 2 + j;
                int r = qr0 - k;
                int r0 = r < -32 ? -32 : (r > 32 ? 32 : r);
                int r1 = (r + 8) < -32 ? -32 : ((r + 8) > 32 ? 32 : (r + 8));
                sacc[nt][j]     += lut[r0 + 32];
                sacc[nt][2 + j] += lut[r1 + 32];
                mx0 = fmaxf(mx0, sacc[nt][j]);
                mx1 = fmaxf(mx1, sacc[nt][2 + j]);
            }
        }
        #pragma unroll
        for (int off = 1; off <= 2; off <<= 1) {
            mx0 = fmaxf(mx0, __shfl_xor_sync(0xffffffffu, mx0, off));
            mx1 = fmaxf(mx1, __shfl_xor_sync(0xffffffffu, mx1, off));
        }
        float mn0 = fmaxf(mrow0, mx0), mn1 = fmaxf(mrow1, mx1);
        float al0 = __expf(mrow0 - mn0), al1 = __expf(mrow1 - mn1);
        mrow0 = mn0; mrow1 = mn1;
        float s0 = 0.f, s1 = 0.f;
        #pragma unroll
        for (int nt = 0; nt < 8; nt++) {
            #pragma unroll
            for (int j = 0; j < 2; j++) {
                float p0 = __expf(sacc[nt][j] - mn0);
                float p1 = __expf(sacc[nt][2 + j] - mn1);
                sacc[nt][j] = p0;  sacc[nt][2 + j] = p1;
                s0 += p0;  s1 += p1;
            }
        }
        #pragma unroll
        for (int off = 1; off <= 2; off <<= 1) {
            s0 += __shfl_xor_sync(0xffffffffu, s0, off);
            s1 += __shfl_xor_sync(0xffffffffu, s1, off);
        }
        lrow0 = lrow0 * al0 + s0;
        lrow1 = lrow1 * al1 + s1;
        #pragma unroll
        for (int nt = 0; nt < 8; nt++) {
            oacc[nt][0] *= al0;  oacc[nt][1] *= al0;
            oacc[nt][2] *= al1;  oacc[nt][3] *= al1;
        }

        // O += Ph*Vh + Pl*Vh + Ph*Vl
        #pragma unroll
        for (int ks = 0; ks < 4; ks++) {
            uint32_t ph[4], pl[4];
            float ra, rb;
            ph[0] = packres(sacc[2*ks][0],   sacc[2*ks][1],   ra, rb); pl[0] = packbf(ra, rb);
            ph[1] = packres(sacc[2*ks][2],   sacc[2*ks][3],   ra, rb); pl[1] = packbf(ra, rb);
            ph[2] = packres(sacc[2*ks+1][0], sacc[2*ks+1][1], ra, rb); pl[2] = packbf(ra, rb);
            ph[3] = packres(sacc[2*ks+1][2], sacc[2*ks+1][3], ra, rb); pl[3] = packbf(ra, rb);
            #pragma unroll
            for (int p = 0; p < 4; p++) {
                uint32_t vr = (uint32_t)((ks*16 + ((lane>>3)&1)*8 + (lane&7)) * 144
                                         + p*32 + ((lane>>4)&1)*16);
                uint32_t h0, h1, h2, h3, l0, l1, l2, l3;
                LDSM4T(h0, h1, h2, h3, sb + 18432 + vr);
                LDSM4T(l0, l1, l2, l3, sb + 27648 + vr);
                uint32_t bh0[2] = {h0, h1}, bh1[2] = {h2, h3};
                uint32_t bl0[2] = {l0, l1}, bl1[2] = {l2, l3};
                MMA16816(oacc[2*p],   ph, bh0);
                MMA16816(oacc[2*p],   pl, bh0);
                MMA16816(oacc[2*p],   ph, bl0);
                MMA16816(oacc[2*p+1], ph, bh1);
                MMA16816(oacc[2*p+1], pl, bh1);
                MMA16816(oacc[2*p+1], ph, bl1);
            }
        }
        __syncthreads();
    }

    float inv0 = 1.0f / lrow0, inv1 = 1.0f / lrow1;
    size_t row0 = ((size_t)b * SEQ + qr0) * EMB + h * HD;
    #pragma unroll
    for (int nt = 0; nt < 8; nt++) {
        int d = nt * 8 + (lane & 3) * 2;
        *(float2*)(&ctx[row0 + d]) =
            make_float2(oacc[nt][0] * inv0, oacc[nt][1] * inv0);
        *(float2*)(&ctx[row0 + (size_t)8 * EMB + d]) =
            make_float2(oacc[nt][2] * inv1, oacc[nt][3] * inv1);
    }
}

// ---------------------------------------------------------------------------
extern "C" void kernel_launch(void* const* d_in, const int* in_sizes, int n_in,
                              void* d_out, int out_size)
{
    const float* x  = (const float*)d_in[0];
    const float* w1 = (const float*)d_in[1];
    const float* b1 = (const float*)d_in[2];
    const float* w2 = (const float*)d_in[3];
    const float* b2 = (const float*)d_in[4];
    const float* rb = (const float*)d_in[5];
    float* out = (float*)d_out;

    float* qkv_p; cudaGetSymbolAddress((void**)&qkv_p, g_qkv);
    float* ctx_p; cudaGetSymbolAddress((void**)&ctx_p, g_ctx);
    __nv_bfloat16 *ah, *al, *bh, *bl, *qh, *ql, *kh, *kl, *vh, *vl;
    cudaGetSymbolAddress((void**)&ah, g_ah);
    cudaGetSymbolAddress((void**)&al, g_al);
    cudaGetSymbolAddress((void**)&bh, g_bh);
    cudaGetSymbolAddress((void**)&bl, g_bl);
    cudaGetSymbolAddress((void**)&qh, g_qh);
    cudaGetSymbolAddress((void**)&ql, g_ql);
    cudaGetSymbolAddress((void**)&kh, g_kh);
    cudaGetSymbolAddress((void**)&kl, g_kl);
    cudaGetSymbolAddress((void**)&vh, g_vh);
    cudaGetSymbolAddress((void**)&vl, g_vl);

    const int MM = BATCH * SEQ;
    const size_t gemm_shm = 2 * (size_t)STG;
    cudaFuncSetAttribute(gemm_hmma, cudaFuncAttributeMaxDynamicSharedMemorySize,
                         (int)gemm_shm);
    cudaFuncSetAttribute(attn_hmma, cudaFuncAttributeMaxDynamicSharedMemorySize,
                         (int)ASMEM);

    bias_kernel<<<1, 96>>>(rb);

    {   // split x, w1
        int n4 = MM * EMB / 4;
        split_kernel<<<(n4 + 255) / 256, 256>>>(x, ah, al, n4);
        n4 = 3 * EMB * EMB / 4;
        split_kernel<<<(n4 + 255) / 256, 256>>>(w1, bh, bl, n4);
    }
    {   // QKV projection
        dim3 g(3 * EMB / 128, MM / 128);
        gemm_hmma<<<g, 512, gemm_shm>>>(ah, al, bh, bl, b1, qkv_p,
                                        MM, 3 * EMB, EMB);
    }
    {   // per-head split
        qkv_split<<<BATCH * SEQ, 384>>>(qkv_p, qh, ql, kh, kl, vh, vl);
    }
    {   // attention
        dim3 g(SEQ / 128, NH, BATCH);
        attn_hmma<<<g, 256, ASMEM>>>(qh, ql, kh, kl, vh, vl, ctx_p);
    }
    {   // split ctx, w2; out projection
        int n4 = MM * EMB / 4;
        split_kernel<<<(n4 + 255) / 256, 256>>>(ctx_p, ah, al, n4);
        n4 = EMB * EMB / 4;
        split_kernel<<<(n4 + 255) / 256, 256>>>(w2, bh, bl, n4);
        dim3 g(EMB / 128, MM / 128);
        gemm_hmma<<<g, 512, gemm_shm>>>(ah, al, bh, bl, b2, out,
                                        MM, EMB, EMB);
    }
}

// round 5
// speedup vs baseline: 2.6919x; 1.0548x over previous
#include <cuda_runtime.h>
#include <cuda_bf16.h>
#include <math.h>
#include <stdint.h>

#define BATCH 4
#define SEQ   2048
#define EMB   1024
#define NH    16
#define HD    64
#define QKV_LD (3*EMB)

// ---------------- scratch (__device__ globals; no allocs allowed) ----------
__device__ float g_qkv[(size_t)BATCH * SEQ * 3 * EMB];
__device__ float g_ctx[(size_t)BATCH * SEQ * EMB];
__device__ float g_bias[65];
__device__ __nv_bfloat16 g_ah[(size_t)BATCH * SEQ * EMB];
__device__ __nv_bfloat16 g_al[(size_t)BATCH * SEQ * EMB];
__device__ __nv_bfloat16 g_bh[(size_t)3 * EMB * EMB];
__device__ __nv_bfloat16 g_bl[(size_t)3 * EMB * EMB];
#define HSZ ((size_t)BATCH * NH * SEQ * HD)
__device__ __nv_bfloat16 g_qh[HSZ], g_ql[HSZ];
__device__ __nv_bfloat16 g_kh[HSZ], g_kl[HSZ];
__device__ __nv_bfloat16 g_vh[HSZ], g_vl[HSZ];

// ---------------- PTX helpers (sm_80-era only: valid on compute_103) -------
__device__ __forceinline__ uint32_t smem_u32(const void* p) {
    uint32_t a;
    asm("{ .reg .u64 t; cvta.to.shared.u64 t, %1; cvt.u32.u64 %0, t; }" : "=r"(a) : "l"(p));
    return a;
}
#define CP16(d, s)   asm volatile("cp.async.cg.shared.global [%0], [%1], 16;" :: "r"(d), "l"(s))
#define CP_COMMIT()  asm volatile("cp.async.commit_group;" ::: "memory")
#define CP_WAIT1()   asm volatile("cp.async.wait_group 1;" ::: "memory")
#define CP_WAIT0()   asm volatile("cp.async.wait_group 0;" ::: "memory")

#define LDSM4(r0, r1, r2, r3, a) \
    asm volatile("ldmatrix.sync.aligned.m8n8.x4.shared.b16 {%0,%1,%2,%3}, [%4];" \
        : "=r"(r0), "=r"(r1), "=r"(r2), "=r"(r3) : "r"(a))
#define LDSM4T(r0, r1, r2, r3, a) \
    asm volatile("ldmatrix.sync.aligned.m8n8.x4.trans.shared.b16 {%0,%1,%2,%3}, [%4];" \
        : "=r"(r0), "=r"(r1), "=r"(r2), "=r"(r3) : "r"(a))

#define MMA16816(d, a, b) \
    asm volatile("mma.sync.aligned.m16n8k16.row.col.f32.bf16.bf16.f32 " \
        "{%0,%1,%2,%3}, {%4,%5,%6,%7}, {%8,%9}, {%0,%1,%2,%3};" \
        : "+f"((d)[0]), "+f"((d)[1]), "+f"((d)[2]), "+f"((d)[3]) \
        : "r"((a)[0]), "r"((a)[1]), "r"((a)[2]), "r"((a)[3]), "r"((b)[0]), "r"((b)[1]))

// ---------------------------------------------------------------------------
__global__ void bias_kernel(const float* __restrict__ rel_bias) {
    int r = threadIdx.x;
    if (r < 65) {
        float s = 0.f;
        #pragma unroll
        for (int h = 0; h < NH; h++) s += rel_bias[r * NH + h];
        g_bias[r] = s * (1.0f / NH);
    }
}

// ---------------------------------------------------------------------------
__global__ __launch_bounds__(256) void split_kernel(
    const float* __restrict__ x, __nv_bfloat16* __restrict__ hi,
    __nv_bfloat16* __restrict__ lo, int n4)
{
    int i = blockIdx.x * blockDim.x + threadIdx.x;
    if (i >= n4) return;
    float4 v = ((const float4*)x)[i];
    __nv_bfloat16 h0 = __float2bfloat16(v.x), h1 = __float2bfloat16(v.y);
    __nv_bfloat16 h2 = __float2bfloat16(v.z), h3 = __float2bfloat16(v.w);
    __nv_bfloat162 H0 = {h0, h1}, H1 = {h2, h3};
    __nv_bfloat162 L0 = {__float2bfloat16(v.x - __bfloat162float(h0)),
                         __float2bfloat16(v.y - __bfloat162float(h1))};
    __nv_bfloat162 L1 = {__float2bfloat16(v.z - __bfloat162float(h2)),
                         __float2bfloat16(v.w - __bfloat162float(h3))};
    ((__nv_bfloat162*)hi)[i*2]   = H0;  ((__nv_bfloat162*)hi)[i*2+1] = H1;
    ((__nv_bfloat162*)lo)[i*2]   = L0;  ((__nv_bfloat162*)lo)[i*2+1] = L1;
}

// ---------------------------------------------------------------------------
// qkv fp32 [B,S,3E]  ->  per-head split bf16 arrays [B,NH,S,D] (q scaled 1/8)
// ---------------------------------------------------------------------------
__global__ __launch_bounds__(384) void qkv_split(
    const float* __restrict__ qkv,
    __nv_bfloat16* __restrict__ qh, __nv_bfloat16* __restrict__ ql,
    __nv_bfloat16* __restrict__ kh, __nv_bfloat16* __restrict__ kl,
    __nv_bfloat16* __restrict__ vh, __nv_bfloat16* __restrict__ vl)
{
    int blk = blockIdx.x;
    int t = threadIdx.x;
    int e0 = t * 8;
    int which = e0 >> 10;
    int h = (e0 & 1023) >> 6;
    int d = e0 & 63;
    const float* src = qkv + (size_t)blk * QKV_LD + e0;
    __nv_bfloat16 *ph, *pl;
    float sc = 1.0f;
    if (which == 0)      { ph = qh; pl = ql; sc = 0.125f; }
    else if (which == 1) { ph = kh; pl = kl; }
    else                 { ph = vh; pl = vl; }
    size_t o = (((size_t)(blk / SEQ) * NH + h) * SEQ + (blk % SEQ)) * HD + d;
    float4 v0 = *(const float4*)src;
    float4 v1 = *(const float4*)(src + 4);
    float vv[8] = {v0.x*sc, v0.y*sc, v0.z*sc, v0.w*sc,
                   v1.x*sc, v1.y*sc, v1.z*sc, v1.w*sc};
    #pragma unroll
    for (int j = 0; j < 4; j++) {
        __nv_bfloat16 a = __float2bfloat16(vv[2*j]);
        __nv_bfloat16 b = __float2bfloat16(vv[2*j+1]);
        __nv_bfloat162 H = {a, b};
        __nv_bfloat162 L = {__float2bfloat16(vv[2*j]   - __bfloat162float(a)),
                            __float2bfloat16(vv[2*j+1] - __bfloat162float(b))};
        *(__nv_bfloat162*)(ph + o + 2*j) = H;
        *(__nv_bfloat162*)(pl + o + 2*j) = L;
    }
}

// ---------------------------------------------------------------------------
// HMMA split-bf16 GEMM v2: 128x128 CTA tile, BK=32, 128 threads,
// 2x2 warp grid (64x64 warp tile) -> halves LDSM traffic; 2 CTAs/SM.
// ---------------------------------------------------------------------------
#define TIL 10240
#define STG (4*TIL)

__global__ __launch_bounds__(128) void gemm_hmma(
    const __nv_bfloat16* __restrict__ Ah, const __nv_bfloat16* __restrict__ Al,
    const __nv_bfloat16* __restrict__ Bh, const __nv_bfloat16* __restrict__ Bl,
    const float* __restrict__ bias, float* __restrict__ C,
    int M, int N, int K)
{
    extern __shared__ char sm[];
    uint32_t smb = smem_u32(sm);
    const int t = threadIdx.x;
    const int lane = t & 31, wid = t >> 5;
    const int wm = wid >> 1, wn = wid & 1;       // 2x2 warp grid, 64x64 tiles
    const int m0 = blockIdx.y * 128, n0 = blockIdx.x * 128;

    auto load_stage = [&](int buf, int k0) {
        uint32_t d = smb + buf * STG;
        #pragma unroll
        for (int c = 0; c < 4; c++) {
            int id = c * 128 + t;
            int row = id >> 2, ch = id & 3;
            uint32_t so = (uint32_t)(row * 80 + ch * 16);
            size_t ao = (size_t)(m0 + row) * K + k0 + ch * 8;
            size_t bo = (size_t)(n0 + row) * K + k0 + ch * 8;
            CP16(d + so,           Ah + ao);
            CP16(d + TIL + so,     Al + ao);
            CP16(d + 2*TIL + so,   Bh + bo);
            CP16(d + 3*TIL + so,   Bl + bo);
        }
    };

    float acc[4][8][4];
    #pragma unroll
    for (int i = 0; i < 4; i++)
        #pragma unroll
        for (int j = 0; j < 8; j++)
            #pragma unroll
            for (int v = 0; v < 4; v++) acc[i][j][v] = 0.f;

    const int NS = K >> 5;
    load_stage(0, 0);
    CP_COMMIT();

    for (int s = 0; s < NS; s++) {
        if (s + 1 < NS) { load_stage((s + 1) & 1, (s + 1) << 5); CP_COMMIT(); CP_WAIT1(); }
        else           { CP_WAIT0(); }
        __syncthreads();

        uint32_t abase = smb + (s & 1) * STG;
        uint32_t bbase = abase + 2 * TIL;

        #pragma unroll
        for (int ks = 0; ks < 2; ks++) {
            uint32_t a_ad[4], b_ad[4];
            #pragma unroll
            for (int mt = 0; mt < 4; mt++)
                a_ad[mt] = abase + (uint32_t)((wm*64 + mt*16 + (lane & 15)) * 80
                                              + ks*32 + (lane >> 4) * 16);
            #pragma unroll
            for (int p = 0; p < 4; p++)
                b_ad[p] = bbase + (uint32_t)((wn*64 + p*16 + (lane >> 4) * 8 + (lane & 7)) * 80
                                             + ks*32 + ((lane >> 3) & 1) * 16);

            uint32_t af[4][4], xf[4][4], bf[8][2];
            // Ah frags + Bh frags
            #pragma unroll
            for (int mt = 0; mt < 4; mt++)
                LDSM4(af[mt][0], af[mt][1], af[mt][2], af[mt][3], a_ad[mt]);
            #pragma unroll
            for (int p = 0; p < 4; p++)
                LDSM4(bf[2*p][0], bf[2*p][1], bf[2*p+1][0], bf[2*p+1][1], b_ad[p]);
            // HH
            #pragma unroll
            for (int mt = 0; mt < 4; mt++)
                #pragma unroll
                for (int j = 0; j < 8; j++) MMA16816(acc[mt][j], af[mt], bf[j]);
            // LH (Al x Bh)
            #pragma unroll
            for (int mt = 0; mt < 4; mt++)
                LDSM4(xf[mt][0], xf[mt][1], xf[mt][2], xf[mt][3], a_ad[mt] + TIL);
            #pragma unroll
            for (int mt = 0; mt < 4; mt++)
                #pragma unroll
                for (int j = 0; j < 8; j++) MMA16816(acc[mt][j], xf[mt], bf[j]);
            // HL (Ah x Bl) — overwrite bf with Bl
            #pragma unroll
            for (int p = 0; p < 4; p++)
                LDSM4(bf[2*p][0], bf[2*p][1], bf[2*p+1][0], bf[2*p+1][1], b_ad[p] + TIL);
            #pragma unroll
            for (int mt = 0; mt < 4; mt++)
                #pragma unroll
                for (int j = 0; j < 8; j++) MMA16816(acc[mt][j], af[mt], bf[j]);
        }
        __syncthreads();
    }

    #pragma unroll
    for (int mt = 0; mt < 4; mt++) {
        int m = m0 + wm*64 + mt*16 + (lane >> 2);
        #pragma unroll
        for (int j = 0; j < 8; j++) {
            int n = n0 + wn*64 + j*8 + (lane & 3) * 2;
            float b0 = bias[n], b1 = bias[n + 1];
            float2 v0 = make_float2(acc[mt][j][0] + b0, acc[mt][j][1] + b1);
            float2 v1 = make_float2(acc[mt][j][2] + b0, acc[mt][j][3] + b1);
            *(float2*)(&C[(size_t)m * N + n])       = v0;
            *(float2*)(&C[(size_t)(m + 8) * N + n]) = v1;
        }
    }
}

// ---------------------------------------------------------------------------
// HMMA flash attention (unchanged from R4)
// ---------------------------------------------------------------------------
#define AQH 0u
#define AQL 18432u
#define AST 36864u
#define ASS 36864u
#define ALUT 110592u
#define ASMEM 110912u

__device__ __forceinline__ uint32_t packres(float a, float b, float& ra, float& rb) {
    __nv_bfloat162 h;
    h.x = __float2bfloat16(a); h.y = __float2bfloat16(b);
    ra = a - __bfloat162float(h.x);
    rb = b - __bfloat162float(h.y);
    return *(uint32_t*)&h;
}
__device__ __forceinline__ uint32_t packbf(float a, float b) {
    __nv_bfloat162 h;
    h.x = __float2bfloat16(a); h.y = __float2bfloat16(b);
    return *(uint32_t*)&h;
}

__global__ __launch_bounds__(256) void attn_hmma(
    const __nv_bfloat16* __restrict__ qh_g, const __nv_bfloat16* __restrict__ ql_g,
    const __nv_bfloat16* __restrict__ kh_g, const __nv_bfloat16* __restrict__ kl_g,
    const __nv_bfloat16* __restrict__ vh_g, const __nv_bfloat16* __restrict__ vl_g,
    float* __restrict__ ctx)
{
    extern __shared__ char sm[];
    uint32_t smb = smem_u32(sm);
    const int t = threadIdx.x, lane = t & 31, wq = t >> 5;
    const int q0 = blockIdx.x * 128, h = blockIdx.y, b = blockIdx.z;

    float* lut = (float*)(sm + ALUT);
    if (t < 65) lut[t] = g_bias[t];

    const size_t hb = ((size_t)b * NH + h) * SEQ;
    const size_t qg = (hb + q0) * HD;

    #pragma unroll
    for (int i = 0; i < 4; i++) {
        int id = t * 4 + i, row = id >> 3, ch = id & 7;
        uint32_t so = (uint32_t)(row * 144 + ch * 16);
        size_t go = qg + (size_t)row * 64 + ch * 8;
        CP16(smb + AQH + so, qh_g + go);
        CP16(smb + AQL + so, ql_g + go);
    }
    auto load_kv = [&](int buf, int j0) {
        uint32_t sb = smb + AST + (uint32_t)buf * ASS;
        size_t gb = (hb + j0) * HD;
        #pragma unroll
        for (int i = 0; i < 2; i++) {
            int id = t * 2 + i, row = id >> 3, ch = id & 7;
            uint32_t so = (uint32_t)(row * 144 + ch * 16);
            size_t go = gb + (size_t)row * 64 + ch * 8;
            CP16(sb + so,         kh_g + go);
            CP16(sb + 9216 + so,  kl_g + go);
            CP16(sb + 18432 + so, vh_g + go);
            CP16(sb + 27648 + so, vl_g + go);
        }
    };
    load_kv(0, 0);
    CP_COMMIT();

    uint32_t qhf[4][4], qlf[4][4];
    float oacc[8][4];
    #pragma unroll
    for (int i = 0; i < 8; i++)
        #pragma unroll
        for (int j = 0; j < 4; j++) oacc[i][j] = 0.f;
    float mrow0 = -1e30f, mrow1 = -1e30f, lrow0 = 0.f, lrow1 = 0.f;

    const int qr0 = q0 + wq * 16 + (lane >> 2);
    const int NT = SEQ / 64;

    for (int jt = 0; jt < NT; jt++) {
        if (jt + 1 < NT) { load_kv((jt + 1) & 1, (jt + 1) * 64); CP_COMMIT(); CP_WAIT1(); }
        else            { CP_WAIT0(); }
        __syncthreads();

        if (jt == 0) {
            #pragma unroll
            for (int ks = 0; ks < 4; ks++) {
                uint32_t ar = (uint32_t)((wq*16 + ((lane>>3)&1)*8 + (lane&7)) * 144
                                         + ks*32 + ((lane>>4)&1)*16);
                LDSM4(qhf[ks][0], qhf[ks][1], qhf[ks][2], qhf[ks][3], smb + AQH + ar);
                LDSM4(qlf[ks][0], qlf[ks][1], qlf[ks][2], qlf[ks][3], smb + AQL + ar);
            }
        }

        uint32_t sb = smb + AST + (uint32_t)(jt & 1) * ASS;
        float sacc[8][4];
        #pragma unroll
        for (int i = 0; i < 8; i++)
            #pragma unroll
            for (int j = 0; j < 4; j++) sacc[i][j] = 0.f;

        #pragma unroll
        for (int ks = 0; ks < 4; ks++) {
            #pragma unroll
            for (int p = 0; p < 4; p++) {
                uint32_t kr = (uint32_t)((p*16 + ((lane>>4)&1)*8 + (lane&7)) * 144
                                         + ks*32 + ((lane>>3)&1)*16);
                uint32_t h0, h1, h2, h3, l0, l1, l2, l3;
                LDSM4(h0, h1, h2, h3, sb + kr);
                LDSM4(l0, l1, l2, l3, sb + 9216 + kr);
                uint32_t bh0[2] = {h0, h1}, bh1[2] = {h2, h3};
                uint32_t bl0[2] = {l0, l1}, bl1[2] = {l2, l3};
                MMA16816(sacc[2*p],   qhf[ks], bh0);
                MMA16816(sacc[2*p],   qlf[ks], bh0);
                MMA16816(sacc[2*p],   qhf[ks], bl0);
                MMA16816(sacc[2*p+1], qhf[ks], bh1);
                MMA16816(sacc[2*p+1], qlf[ks], bh1);
                MMA16816(sacc[2*p+1], qhf[ks], bl1);
            }
        }

        float mx0 = -1e30f, mx1 = -1e30f;
        #pragma unroll
        for (int nt = 0; nt < 8; nt++) {
            #pragma unroll
            for (int j = 0; j < 2; j++) {
                int k = jt * 64 + nt * 8 + (lane & 3) * 2 + j;
                int r = qr0 - k;
                int r0 = r < -32 ? -32 : (r > 32 ? 32 : r);
                int r1 = (r + 8) < -32 ? -32 : ((r + 8) > 32 ? 32 : (r + 8));
                sacc[nt][j]     += lut[r0 + 32];
                sacc[nt][2 + j] += lut[r1 + 32];
                mx0 = fmaxf(mx0, sacc[nt][j]);
                mx1 = fmaxf(mx1, sacc[nt][2 + j]);
            }
        }
        #pragma unroll
        for (int off = 1; off <= 2; off <<= 1) {
            mx0 = fmaxf(mx0, __shfl_xor_sync(0xffffffffu, mx0, off));
            mx1 = fmaxf(mx1, __shfl_xor_sync(0xffffffffu, mx1, off));
        }
        float mn0 = fmaxf(mrow0, mx0), mn1 = fmaxf(mrow1, mx1);
        float al0 = __expf(mrow0 - mn0), al1 = __expf(mrow1 - mn1);
        mrow0 = mn0; mrow1 = mn1;
        float s0 = 0.f, s1 = 0.f;
        #pragma unroll
        for (int nt = 0; nt < 8; nt++) {
            #pragma unroll
            for (int j = 0; j < 2; j++) {
                float p0 = __expf(sacc[nt][j] - mn0);
                float p1 = __expf(sacc[nt][2 + j] - mn1);
                sacc[nt][j] = p0;  sacc[nt][2 + j] = p1;
                s0 += p0;  s1 += p1;
            }
        }
        #pragma unroll
        for (int off = 1; off <= 2; off <<= 1) {
            s0 += __shfl_xor_sync(0xffffffffu, s0, off);
            s1 += __shfl_xor_sync(0xffffffffu, s1, off);
        }
        lrow0 = lrow0 * al0 + s0;
        lrow1 = lrow1 * al1 + s1;
        #pragma unroll
        for (int nt = 0; nt < 8; nt++) {
            oacc[nt][0] *= al0;  oacc[nt][1] *= al0;
            oacc[nt][2] *= al1;  oacc[nt][3] *= al1;
        }

        #pragma unroll
        for (int ks = 0; ks < 4; ks++) {
            uint32_t ph[4], pl[4];
            float ra, rb;
            ph[0] = packres(sacc[2*ks][0],   sacc[2*ks][1],   ra, rb); pl[0] = packbf(ra, rb);
            ph[1] = packres(sacc[2*ks][2],   sacc[2*ks][3],   ra, rb); pl[1] = packbf(ra, rb);
            ph[2] = packres(sacc[2*ks+1][0], sacc[2*ks+1][1], ra, rb); pl[2] = packbf(ra, rb);
            ph[3] = packres(sacc[2*ks+1][2], sacc[2*ks+1][3], ra, rb); pl[3] = packbf(ra, rb);
            #pragma unroll
            for (int p = 0; p < 4; p++) {
                uint32_t vr = (uint32_t)((ks*16 + ((lane>>3)&1)*8 + (lane&7)) * 144
                                         + p*32 + ((lane>>4)&1)*16);
                uint32_t h0, h1, h2, h3, l0, l1, l2, l3;
                LDSM4T(h0, h1, h2, h3, sb + 18432 + vr);
                LDSM4T(l0, l1, l2, l3, sb + 27648 + vr);
                uint32_t bh0[2] = {h0, h1}, bh1[2] = {h2, h3};
                uint32_t bl0[2] = {l0, l1}, bl1[2] = {l2, l3};
                MMA16816(oacc[2*p],   ph, bh0);
                MMA16816(oacc[2*p],   pl, bh0);
                MMA16816(oacc[2*p],   ph, bl0);
                MMA16816(oacc[2*p+1], ph, bh1);
                MMA16816(oacc[2*p+1], pl, bh1);
                MMA16816(oacc[2*p+1], ph, bl1);
            }
        }
        __syncthreads();
    }

    float inv0 = 1.0f / lrow0, inv1 = 1.0f / lrow1;
    size_t row0 = ((size_t)b * SEQ + qr0) * EMB + h * HD;
    #pragma unroll
    for (int nt = 0; nt < 8; nt++) {
        int d = nt * 8 + (lane & 3) * 2;
        *(float2*)(&ctx[row0 + d]) =
            make_float2(oacc[nt][0] * inv0, oacc[nt][1] * inv0);
        *(float2*)(&ctx[row0 + (size_t)8 * EMB + d]) =
            make_float2(oacc[nt][2] * inv1, oacc[nt][3] * inv1);
    }
}

// ---------------------------------------------------------------------------
extern "C" void kernel_launch(void* const* d_in, const int* in_sizes, int n_in,
                              void* d_out, int out_size)
{
    const float* x  = (const float*)d_in[0];
    const float* w1 = (const float*)d_in[1];
    const float* b1 = (const float*)d_in[2];
    const float* w2 = (const float*)d_in[3];
    const float* b2 = (const float*)d_in[4];
    const float* rb = (const float*)d_in[5];
    float* out = (float*)d_out;

    float* qkv_p; cudaGetSymbolAddress((void**)&qkv_p, g_qkv);
    float* ctx_p; cudaGetSymbolAddress((void**)&ctx_p, g_ctx);
    __nv_bfloat16 *ah, *al, *bh, *bl, *qh, *ql, *kh, *kl, *vh, *vl;
    cudaGetSymbolAddress((void**)&ah, g_ah);
    cudaGetSymbolAddress((void**)&al, g_al);
    cudaGetSymbolAddress((void**)&bh, g_bh);
    cudaGetSymbolAddress((void**)&bl, g_bl);
    cudaGetSymbolAddress((void**)&qh, g_qh);
    cudaGetSymbolAddress((void**)&ql, g_ql);
    cudaGetSymbolAddress((void**)&kh, g_kh);
    cudaGetSymbolAddress((void**)&kl, g_kl);
    cudaGetSymbolAddress((void**)&vh, g_vh);
    cudaGetSymbolAddress((void**)&vl, g_vl);

    const int MM = BATCH * SEQ;
    const size_t gemm_shm = 2 * (size_t)STG;   // 81920 B
    cudaFuncSetAttribute(gemm_hmma, cudaFuncAttributeMaxDynamicSharedMemorySize,
                         (int)gemm_shm);
    cudaFuncSetAttribute(attn_hmma, cudaFuncAttributeMaxDynamicSharedMemorySize,
                         (int)ASMEM);

    bias_kernel<<<1, 96>>>(rb);

    {
        int n4 = MM * EMB / 4;
        split_kernel<<<(n4 + 255) / 256, 256>>>(x, ah, al, n4);
        n4 = 3 * EMB * EMB / 4;
        split_kernel<<<(n4 + 255) / 256, 256>>>(w1, bh, bl, n4);
    }
    {
        dim3 g(3 * EMB / 128, MM / 128);
        gemm_hmma<<<g, 128, gemm_shm>>>(ah, al, bh, bl, b1, qkv_p,
                                        MM, 3 * EMB, EMB);
    }
    {
        qkv_split<<<BATCH * SEQ, 384>>>(qkv_p, qh, ql, kh, kl, vh, vl);
    }
    {
        dim3 g(SEQ / 128, NH, BATCH);
        attn_hmma<<<g, 256, ASMEM>>>(qh, ql, kh, kl, vh, vl, ctx_p);
    }
    {
        int n4 = MM * EMB / 4;
        split_kernel<<<(n4 + 255) / 256, 256>>>(ctx_p, ah, al, n4);
        n4 = EMB * EMB / 4;
        split_kernel<<<(n4 + 255) / 256, 256>>>(w2, bh, bl, n4);
        dim3 g(EMB / 128, MM / 128);
        gemm_hmma<<<g, 128, gemm_shm>>>(ah, al, bh, bl, b2, out,
                                        MM, EMB, EMB);
    }
}